// round 14
// baseline (speedup 1.0000x reference)
#include <cuda_runtime.h>
#include <cuda_fp16.h>
#include <cstdint>

#define DDIM 128
#define KCB  1024
#define MT   128
#define NC2  128              // codes per iteration
#define NITER 8
#define TH   256

#define ASTRIDE 272
#define AMAT   (128 * ASTRIDE)        // 34816: A (h term only)
#define BMAT   (128 * ASTRIDE)        // 34816 per stage (128 codes)
#define A_OFF  0
#define B_OFF  AMAT                   // 2 stages: 34816..104448
#define EN_OFF (B_OFF + 2 * BMAT)     // 104448: 1024 floats
#define T_OFF  (EN_OFF + 4096)        // 108544: 128 floats
#define SMEM_TOTAL (T_OFF + 512)      // 109056 -> 2 CTAs/SM
// post-mainloop aliases
#define RV1_OFF B_OFF
#define RV2_OFF (B_OFF + 1024)
#define RI1_OFF (B_OFF + 2048)
#define SBI_OFF EN_OFF

__device__ float g_enorm[KCB];
__device__ int   g_iME;
__device__ int   g_iMEL;
__device__ int   g_cnt;
__device__ int   g_list[96000];
__device__ __align__(16) unsigned short g_fh[KCB * DDIM];  // fp16(32*embed)

// ---------------- PTX helpers ----------------
static __device__ __forceinline__ uint32_t smem_u32(const void* p) {
    uint32_t a;
    asm("{ .reg .u64 t; cvta.to.shared.u64 t, %1; cvt.u32.u64 %0, t; }"
        : "=r"(a) : "l"(p));
    return a;
}
static __device__ __forceinline__ void ldsm4(uint32_t* r, uint32_t a) {
    asm volatile("ldmatrix.sync.aligned.m8n8.x4.shared.b16 {%0,%1,%2,%3}, [%4];"
                 : "=r"(r[0]), "=r"(r[1]), "=r"(r[2]), "=r"(r[3]) : "r"(a));
}
static __device__ __forceinline__ void mma16816(float* c, const uint32_t* a,
                                                const uint32_t* b2) {
    asm volatile(
        "mma.sync.aligned.m16n8k16.row.col.f32.f16.f16.f32 "
        "{%0,%1,%2,%3}, {%4,%5,%6,%7}, {%8,%9}, {%0,%1,%2,%3};"
        : "+f"(c[0]), "+f"(c[1]), "+f"(c[2]), "+f"(c[3])
        : "r"(a[0]), "r"(a[1]), "r"(a[2]), "r"(a[3]), "r"(b2[0]), "r"(b2[1]));
}
static __device__ __forceinline__ void cpasync16(uint32_t dst, const void* src) {
    asm volatile("cp.async.cg.shared.global [%0], [%1], 16;" :: "r"(dst), "l"(src));
}
static __device__ __forceinline__ void cp_commit() {
    asm volatile("cp.async.commit_group;" ::: "memory");
}
static __device__ __forceinline__ void cp_wait1() {
    asm volatile("cp.async.wait_group 1;" ::: "memory");
}
static __device__ __forceinline__ void cp_wait0() {
    asm volatile("cp.async.wait_group 0;" ::: "memory");
}
static __device__ __forceinline__ unsigned short hbits(__half h) {
    return *reinterpret_cast<unsigned short*>(&h);
}

// ---------------- prep: split + norms + maxima + counter reset ----------------
__global__ void prep_kernel(const float* __restrict__ embed) {
    int i = blockIdx.x * blockDim.x + threadIdx.x;
    if (i < KCB * DDIM)
        g_fh[i] = hbits(__float2half_rn(embed[i] * 32.0f));
    if (blockIdx.x == 0 && threadIdx.x == 0) g_cnt = 0;
    if (blockIdx.x < 4) {
        int k = blockIdx.x * blockDim.x + threadIdx.x;   // 0..1023
        const float4* row = reinterpret_cast<const float4*>(embed + (long long)k * DDIM);
        float ne = 0.f, nel = 0.f;
        #pragma unroll
        for (int j = 0; j < DDIM / 4; j++) {
            float4 v = row[j];
            float vv[4] = {v.x, v.y, v.z, v.w};
            #pragma unroll
            for (int q = 0; q < 4; q++) {
                float e = vv[q];
                float E = e * 32.0f;
                float el = E - __half2float(__float2half_rn(E));
                ne  = fmaf(e, e, ne);
                nel = fmaf(el, el, nel);
            }
        }
        g_enorm[k] = ne;
        atomicMax(&g_iME,  __float_as_int(sqrtf(ne)));
        atomicMax(&g_iMEL, __float_as_int(sqrtf(nel)));
    }
}

// ---------------- B loader: 128 codes x 256B per stage ----------------
static __device__ __forceinline__ void load_b(uint32_t sb, int c, int stage, int tid) {
    uint32_t dbase = sb + B_OFF + (uint32_t)stage * BMAT;
    const char* gb = reinterpret_cast<const char*>(g_fh);
    #pragma unroll
    for (int i = 0; i < 8; i++) {
        int e = tid + i * TH;          // 0..2047
        int rr  = e >> 4;              // 0..127
        int seg = e & 15;
        const char* src = gb + ((size_t)c * NC2 + rr) * 256 + seg * 16;
        uint32_t dst = dbase + (uint32_t)rr * ASTRIDE + seg * 16;
        cpasync16(dst, src);
    }
}

// ---------------- phase 1: h*h GEMM, certified top-1 ----------------
__global__ __launch_bounds__(TH, 2)
void vq1_kernel(const float* __restrict__ x, const float* __restrict__ embed,
                float* __restrict__ out, int nrows, int write_idx) {
    extern __shared__ __align__(16) char smm[];
    const uint32_t sb = smem_u32(smm);
    const int tid = threadIdx.x;
    const int l = tid & 31;
    const int w = tid >> 5;
    const int wm = w & 3;      // 4 M-warps: rows wm*32
    const int wn = w >> 2;     // 2 N-warps: cols wn*64 within 128-chunk
    const int rowBase = blockIdx.x * MT;

    float* s_en = reinterpret_cast<float*>(smm + EN_OFF);
    float* s_T  = reinterpret_cast<float*>(smm + T_OFF);
    #pragma unroll
    for (int i = 0; i < 4; i++) s_en[tid + i * TH] = g_enorm[tid + i * TH];

    load_b(sb, 0, 0, tid); cp_commit();
    load_b(sb, 1, 1, tid); cp_commit();

    const float ME    = __int_as_float(g_iME);
    const float MEL32 = __int_as_float(g_iMEL) * 0.03125f;

    // A: h term to smem; per-row ||xh||, ||x - xh|| -> certification threshold
    {
        const float4* gx = reinterpret_cast<const float4*>(x + (long long)rowBase * DDIM);
        #pragma unroll
        for (int i = 0; i < 16; i++) {
            int fi = tid + i * TH;
            int r = fi >> 5;
            float4 v = gx[fi];
            float vv[4] = {v.x, v.y, v.z, v.w};
            unsigned short hb[4];
            float nh = 0.f, nr = 0.f;
            #pragma unroll
            for (int j = 0; j < 4; j++) {
                __half h = __float2half_rn(vv[j]);
                float hf = __half2float(h);
                float rr = vv[j] - hf;
                hb[j] = hbits(h);
                nh = fmaf(hf, hf, nh);
                nr = fmaf(rr, rr, nr);
            }
            uint32_t off = (uint32_t)r * ASTRIDE + (uint32_t)(fi & 31) * 8;
            uint2 uh = { (uint32_t)hb[0] | ((uint32_t)hb[1] << 16),
                         (uint32_t)hb[2] | ((uint32_t)hb[3] << 16) };
            *reinterpret_cast<uint2*>(smm + A_OFF + off) = uh;
            #pragma unroll
            for (int o = 16; o > 0; o >>= 1) {
                nh += __shfl_xor_sync(0xffffffffu, nh, o);
                nr += __shfl_xor_sync(0xffffffffu, nr, o);
            }
            if (l == 0)
                s_T[r] = 4.08f * (sqrtf(nh) * MEL32 + sqrtf(nr) * ME) + 1.5e-3f;
        }
    }

    // per-thread top-2 per (mi,h) slot
    float b1[4], b2[4];
    int   i1[4];
    #pragma unroll
    for (int s = 0; s < 4; s++) { b1[s] = -3.4e38f; b2[s] = -3.4e38f; i1[s] = 0; }

    const uint32_t aLane = (uint32_t)((l & 15) * ASTRIDE + ((l >> 4) & 1) * 16);
    const uint32_t bLane = (uint32_t)((((l & 7) + ((l >> 4) << 3)) * ASTRIDE) + ((l >> 3) & 1) * 16);
    const uint32_t aBase = sb + A_OFF + (uint32_t)wm * 8704 + aLane;

    for (int c = 0; c < NITER; c++) {
        if (c + 1 < NITER) cp_wait1(); else cp_wait0();
        __syncthreads();           // B stage (c&1) ready; A visible on first iter

        float acc[2][8][4];
        #pragma unroll
        for (int mi = 0; mi < 2; mi++)
            #pragma unroll
            for (int ni = 0; ni < 8; ni++)
                #pragma unroll
                for (int k = 0; k < 4; k++) acc[mi][ni][k] = 0.f;

        const uint32_t bBase = sb + B_OFF + (uint32_t)(c & 1) * BMAT
                             + (uint32_t)wn * (64 * ASTRIDE) + bLane;
        #pragma unroll
        for (int ks = 0; ks < 8; ks++) {
            uint32_t ak = aBase + (uint32_t)ks * 32;
            uint32_t bk = bBase + (uint32_t)ks * 32;
            uint32_t Ah[2][4];
            ldsm4(Ah[0], ak);  ldsm4(Ah[1], ak + 4352);
            uint32_t Bh[4][4];
            #pragma unroll
            for (int j = 0; j < 4; j++) ldsm4(Bh[j], bk + (uint32_t)j * 4352);
            #pragma unroll
            for (int mi = 0; mi < 2; mi++)
                #pragma unroll
                for (int j = 0; j < 4; j++)
                    #pragma unroll
                    for (int ah = 0; ah < 2; ah++)
                        mma16816(acc[mi][j * 2 + ah], Ah[mi], &Bh[j][2 * ah]);
        }

        __syncthreads();           // all warps done reading stage (c&1)
        if (c + 2 < NITER) { load_b(sb, c + 2, c & 1, tid); cp_commit(); }

        // epilogue: s = acc/16 - ||e||^2 ; top-2 update (overlaps cp flight)
        const int cb = c * NC2;
        #pragma unroll
        for (int mi = 0; mi < 2; mi++)
            #pragma unroll
            for (int ni = 0; ni < 8; ni++) {
                int col0 = cb + wn * 64 + ni * 8 + (l & 3) * 2;
                float2 en = *reinterpret_cast<float2*>(&s_en[col0]);
                #pragma unroll
                for (int h = 0; h < 2; h++) {
                    int s = mi * 2 + h;
                    float v0 = fmaf(acc[mi][ni][2 * h + 0], 0.0625f, -en.x);
                    float v1 = fmaf(acc[mi][ni][2 * h + 1], 0.0625f, -en.y);
                    if (v0 > b1[s]) { b2[s] = b1[s]; b1[s] = v0; i1[s] = col0; }
                    else if (v0 > b2[s]) b2[s] = v0;
                    if (v1 > b1[s]) { b2[s] = b1[s]; b1[s] = v1; i1[s] = col0 + 1; }
                    else if (v1 > b2[s]) b2[s] = v1;
                }
            }
    }

    // ---- quad-shfl top-2 merge, stage per-wn into smem ----
    __syncthreads();
    float* rv1 = reinterpret_cast<float*>(smm + RV1_OFF);
    float* rv2 = reinterpret_cast<float*>(smm + RV2_OFF);
    int*   ri1 = reinterpret_cast<int*>(smm + RI1_OFF);
    #pragma unroll
    for (int s = 0; s < 4; s++) {
        float v1 = b1[s], v2 = b2[s];
        int   k1 = i1[s];
        #pragma unroll
        for (int off = 1; off < 4; off <<= 1) {
            float ov1 = __shfl_xor_sync(0xffffffffu, v1, off);
            float ov2 = __shfl_xor_sync(0xffffffffu, v2, off);
            int   ok1 = __shfl_xor_sync(0xffffffffu, k1, off);
            if (ov1 > v1 || (ov1 == v1 && ok1 < k1)) {
                v2 = fmaxf(v1, ov2); v1 = ov1; k1 = ok1;
            } else {
                v2 = fmaxf(v2, ov1);
            }
        }
        if ((l & 3) == 0) {
            int mi = s >> 1, h = s & 1;
            int row = wm * 32 + mi * 16 + (l >> 2) + h * 8;
            rv1[wn * 128 + row] = v1;
            rv2[wn * 128 + row] = v2;
            ri1[wn * 128 + row] = k1;
        }
    }
    __syncthreads();

    // ---- final merge of 2 N-halves, certify or flag ----
    int* sbi = reinterpret_cast<int*>(smm + SBI_OFF);
    if (tid < 128) {
        float va = rv1[tid],       vb = rv1[128 + tid];
        float wa = rv2[tid],       wb = rv2[128 + tid];
        int   ka = ri1[tid],       kb = ri1[128 + tid];
        int   kwin;
        float m1;
        if (vb > va || (vb == va && kb < ka)) { m1 = vb; kwin = kb; }
        else                                  { m1 = va; kwin = ka; }
        float m2 = fmaxf(fmaxf(fminf(va, vb), wa), wb);
        sbi[tid] = kwin;
        if (write_idx)
            out[(long long)nrows * DDIM + rowBase + tid] = (float)kwin;
        if (m1 - m2 <= s_T[tid]) {
            int pos = atomicAdd(&g_cnt, 1);
            g_list[pos] = rowBase + tid;
        }
    }
    __syncthreads();

    // ---- gather winning codewords ----
    {
        float4* go = reinterpret_cast<float4*>(out);
        const float4* ge = reinterpret_cast<const float4*>(embed);
        #pragma unroll
        for (int i = 0; i < 16; i++) {
            int idx = tid + i * TH;
            int row = idx >> 5;
            int c4  = idx & 31;
            int k = sbi[row];
            go[((long long)(rowBase + row) << 5) + c4] = ge[(k << 5) + c4];
        }
    }
}

// ---------------- phase 2: exact fp32 rescan of flagged rows ----------------
__global__ __launch_bounds__(256, 4)
void fb_kernel(const float* __restrict__ x, const float* __restrict__ embed,
               float* __restrict__ out, int nrows, int write_idx) {
    __shared__ float sx[32][132];
    __shared__ float se[32 * 128];
    __shared__ float sen[KCB];
    __shared__ int   srows[32];
    __shared__ float sredv[8][32];
    __shared__ int   sredi[8][32];
    __shared__ int   sfin[32];

    const int tid = threadIdx.x;
    const int l = tid & 31;
    const int w = tid >> 5;

    #pragma unroll
    for (int i = 0; i < 4; i++) sen[tid + i * 256] = g_enorm[tid + i * 256];
    const int cnt = g_cnt;

    for (int b = blockIdx.x; b * 32 < cnt; b += gridDim.x) {
        int n = cnt - b * 32; if (n > 32) n = 32;
        if (tid < 32) srows[tid] = (tid < n) ? g_list[b * 32 + tid] : g_list[b * 32];
        __syncthreads();
        #pragma unroll
        for (int i = 0; i < 4; i++) {
            int idx = tid + i * 256;
            int j = idx >> 5, seg = idx & 31;
            float4 v = reinterpret_cast<const float4*>(x)[(long long)srows[j] * 32 + seg];
            *reinterpret_cast<float4*>(&sx[j][seg * 4]) = v;
        }

        float best = -3.4e38f;
        int   bi = 0;
        for (int ch = 0; ch < 32; ch++) {
            __syncthreads();
            #pragma unroll
            for (int i = 0; i < 4; i++) {
                int idx = tid + i * 256;
                int cr = idx >> 5, seg = idx & 31;
                float4 v = reinterpret_cast<const float4*>(embed)[((long long)ch * 32 + cr) * 32 + seg];
                *reinterpret_cast<float4*>(&se[cr * 128 + seg * 4]) = v;
            }
            __syncthreads();
            float acc[4] = {0.f, 0.f, 0.f, 0.f};
            #pragma unroll 8
            for (int d4 = 0; d4 < 32; d4++) {
                float4 xv = *reinterpret_cast<float4*>(&sx[l][d4 * 4]);
                #pragma unroll
                for (int m = 0; m < 4; m++) {
                    float4 ev = *reinterpret_cast<float4*>(&se[(w * 4 + m) * 128 + d4 * 4]);
                    acc[m] = fmaf(xv.x, ev.x, acc[m]);
                    acc[m] = fmaf(xv.y, ev.y, acc[m]);
                    acc[m] = fmaf(xv.z, ev.z, acc[m]);
                    acc[m] = fmaf(xv.w, ev.w, acc[m]);
                }
            }
            #pragma unroll
            for (int m = 0; m < 4; m++) {
                int k = ch * 32 + w * 4 + m;
                float s = fmaf(2.f, acc[m], -sen[k]);
                if (s > best || (s == best && k < bi)) { best = s; bi = k; }
            }
        }
        sredv[w][l] = best;
        sredi[w][l] = bi;
        __syncthreads();
        if (tid < 32) {
            float bv = sredv[0][tid];
            int   bk = sredi[0][tid];
            #pragma unroll
            for (int q = 1; q < 8; q++) {
                float v = sredv[q][tid];
                int   k = sredi[q][tid];
                if (v > bv || (v == bv && k < bk)) { bv = v; bk = k; }
            }
            sfin[tid] = bk;
            if (tid < n && write_idx)
                out[(long long)nrows * DDIM + srows[tid]] = (float)bk;
        }
        __syncthreads();
        #pragma unroll
        for (int i = 0; i < 4; i++) {
            int idx = tid + i * 256;
            int j = idx >> 5, c4 = idx & 31;
            if (j < n) {
                int k = sfin[j];
                reinterpret_cast<float4*>(out)[(long long)srows[j] * 32 + c4] =
                    reinterpret_cast<const float4*>(embed)[(long long)k * 32 + c4];
            }
        }
        __syncthreads();
    }
}

extern "C" void kernel_launch(void* const* d_in, const int* in_sizes, int n_in,
                              void* d_out, int out_size) {
    const float* x     = (const float*)d_in[0];
    const float* embed = (const float*)d_in[1];
    float* out = (float*)d_out;

    int nrows = in_sizes[0] / DDIM;  // 96000
    int write_idx = (out_size >= nrows * DDIM + nrows) ? 1 : 0;

    prep_kernel<<<(KCB * DDIM + 255) / 256, 256>>>(embed);

    cudaFuncSetAttribute(vq1_kernel,
                         cudaFuncAttributeMaxDynamicSharedMemorySize, SMEM_TOTAL);
    vq1_kernel<<<nrows / MT, TH, SMEM_TOTAL>>>(x, embed, out, nrows, write_idx);

    fb_kernel<<<296, 256>>>(x, embed, out, nrows, write_idx);
}

// round 16
// speedup vs baseline: 1.2899x; 1.2899x over previous
#include <cuda_runtime.h>
#include <cuda_fp16.h>
#include <cstdint>

#define DDIM 128
#define KCB  1024
#define MT   128
#define NC   64
#define NCHUNK 16
#define TH   256

#define ASTRIDE 272
#define AMAT   (128 * ASTRIDE)        // 34816: A (h only)
#define BMAT   (64 * ASTRIDE)         // 17408 per term
#define BSTAGE (2 * BMAT)             // 34816 per stage (h+l)
#define A_OFF  0
#define B_OFF  AMAT                   // 2 stages: 34816..104448
#define EN_OFF (B_OFF + 2 * BSTAGE)   // 104448: 1024 floats
#define T_OFF  (EN_OFF + 4096)        // 108544: 128 floats
#define SMEM_TOTAL (T_OFF + 512)      // 109056 -> 2 CTAs/SM
// post-mainloop aliases (B region is dead after the loop)
#define RV1_OFF B_OFF
#define RV2_OFF (B_OFF + 1024)
#define RI1_OFF (B_OFF + 2048)
#define SBI_OFF EN_OFF

__device__ float g_enorm[KCB];
__device__ int   g_iME;               // max ||e|| (float bits, >=0; idempotent)
__device__ int   g_cnt;
__device__ int   g_list[96000];
__device__ __align__(16) unsigned short g_fh[KCB * DDIM];  // fp16(32e)
__device__ __align__(16) unsigned short g_fl[KCB * DDIM];  // fp16(32e - fp16(32e))

// ---------------- PTX helpers ----------------
static __device__ __forceinline__ uint32_t smem_u32(const void* p) {
    uint32_t a;
    asm("{ .reg .u64 t; cvta.to.shared.u64 t, %1; cvt.u32.u64 %0, t; }"
        : "=r"(a) : "l"(p));
    return a;
}
static __device__ __forceinline__ void ldsm4(uint32_t* r, uint32_t a) {
    asm volatile("ldmatrix.sync.aligned.m8n8.x4.shared.b16 {%0,%1,%2,%3}, [%4];"
                 : "=r"(r[0]), "=r"(r[1]), "=r"(r[2]), "=r"(r[3]) : "r"(a));
}
static __device__ __forceinline__ void mma16816(float* c, const uint32_t* a,
                                                const uint32_t* b2) {
    asm volatile(
        "mma.sync.aligned.m16n8k16.row.col.f32.f16.f16.f32 "
        "{%0,%1,%2,%3}, {%4,%5,%6,%7}, {%8,%9}, {%0,%1,%2,%3};"
        : "+f"(c[0]), "+f"(c[1]), "+f"(c[2]), "+f"(c[3])
        : "r"(a[0]), "r"(a[1]), "r"(a[2]), "r"(a[3]), "r"(b2[0]), "r"(b2[1]));
}
static __device__ __forceinline__ void cpasync16(uint32_t dst, const void* src) {
    asm volatile("cp.async.cg.shared.global [%0], [%1], 16;" :: "r"(dst), "l"(src));
}
static __device__ __forceinline__ void cp_commit() {
    asm volatile("cp.async.commit_group;" ::: "memory");
}
static __device__ __forceinline__ void cp_wait1() {
    asm volatile("cp.async.wait_group 1;" ::: "memory");
}
static __device__ __forceinline__ void cp_wait0() {
    asm volatile("cp.async.wait_group 0;" ::: "memory");
}
static __device__ __forceinline__ unsigned short hbits(__half h) {
    return *reinterpret_cast<unsigned short*>(&h);
}

// ---------------- prep: split + ||e||^2 + max||e|| + counter reset ----------------
__global__ void prep_kernel(const float* __restrict__ embed) {
    int i = blockIdx.x * blockDim.x + threadIdx.x;
    if (i < KCB * DDIM) {
        float E = embed[i] * 32.0f;
        __half h = __float2half_rn(E);
        float El = E - __half2float(h);      // exact (Sterbenz)
        g_fh[i] = hbits(h);
        g_fl[i] = hbits(__float2half_rn(El));
    }
    if (blockIdx.x == 0 && threadIdx.x == 0) g_cnt = 0;
    if (blockIdx.x < 4) {
        int k = blockIdx.x * blockDim.x + threadIdx.x;   // 0..1023
        const float4* row = reinterpret_cast<const float4*>(embed + (long long)k * DDIM);
        float ne = 0.f;
        #pragma unroll
        for (int j = 0; j < DDIM / 4; j++) {
            float4 v = row[j];
            ne = fmaf(v.x, v.x, ne); ne = fmaf(v.y, v.y, ne);
            ne = fmaf(v.z, v.z, ne); ne = fmaf(v.w, v.w, ne);
        }
        g_enorm[k] = ne;
        atomicMax(&g_iME, __float_as_int(sqrtf(ne)));
    }
}

// ---------------- B loader: one stage = 2 terms x 64 rows x 256B ----------------
static __device__ __forceinline__ void load_b(uint32_t sb, int c, int stage, int tid) {
    uint32_t dbase = sb + B_OFF + (uint32_t)stage * BSTAGE;
    #pragma unroll
    for (int i = 0; i < 8; i++) {
        int e = tid + i * TH;          // 0..2047 (2 terms x 64 rows x 16 segs)
        int t   = e >> 10;
        int rr  = (e >> 4) & 63;
        int seg = e & 15;
        const char* gb = t ? reinterpret_cast<const char*>(g_fl)
                           : reinterpret_cast<const char*>(g_fh);
        const char* src = gb + ((size_t)c * NC + rr) * 256 + seg * 16;
        uint32_t dst = dbase + (uint32_t)t * BMAT + (uint32_t)rr * ASTRIDE + seg * 16;
        cpasync16(dst, src);
    }
}

// ---------------- phase 1: 2-pass GEMM (hh + hl), certified top-1 ----------------
__global__ __launch_bounds__(TH, 2)
void vq1_kernel(const float* __restrict__ x, const float* __restrict__ embed,
                float* __restrict__ out, int nrows, int write_idx) {
    extern __shared__ __align__(16) char smm[];
    const uint32_t sb = smem_u32(smm);
    const int tid = threadIdx.x;
    const int l = tid & 31;
    const int w = tid >> 5;
    const int wm = w & 3;      // rows wm*32
    const int wn = w >> 2;     // cols wn*32 within 64-chunk
    const int rowBase = blockIdx.x * MT;

    float* s_en = reinterpret_cast<float*>(smm + EN_OFF);
    float* s_T  = reinterpret_cast<float*>(smm + T_OFF);
    #pragma unroll
    for (int i = 0; i < 4; i++) s_en[tid + i * TH] = g_enorm[tid + i * TH];

    load_b(sb, 0, 0, tid); cp_commit();
    load_b(sb, 1, 1, tid); cp_commit();

    const float ME = __int_as_float(g_iME);

    // A: h term to smem; exact per-row ||x - fp16(x)|| -> threshold
    {
        const float4* gx = reinterpret_cast<const float4*>(x + (long long)rowBase * DDIM);
        #pragma unroll
        for (int i = 0; i < 16; i++) {
            int fi = tid + i * TH;
            int r = fi >> 5;
            float4 v = gx[fi];
            float vv[4] = {v.x, v.y, v.z, v.w};
            unsigned short hb[4];
            float nr = 0.f;
            #pragma unroll
            for (int j = 0; j < 4; j++) {
                __half h = __float2half_rn(vv[j]);
                float rr = vv[j] - __half2float(h);   // exact residual
                hb[j] = hbits(h);
                nr = fmaf(rr, rr, nr);
            }
            uint32_t off = (uint32_t)r * ASTRIDE + (uint32_t)(fi & 31) * 8;
            uint2 uh = { (uint32_t)hb[0] | ((uint32_t)hb[1] << 16),
                         (uint32_t)hb[2] | ((uint32_t)hb[3] << 16) };
            *reinterpret_cast<uint2*>(smm + A_OFF + off) = uh;
            #pragma unroll
            for (int o = 16; o > 0; o >>= 1)
                nr += __shfl_xor_sync(0xffffffffu, nr, o);
            if (l == 0)
                s_T[r] = 4.05f * sqrtf(nr) * ME + 3e-4f;
        }
    }

    // per-thread top-2 per (mi,h) slot
    float b1[4], b2[4];
    int   i1[4];
    #pragma unroll
    for (int s = 0; s < 4; s++) { b1[s] = -3.4e38f; b2[s] = -3.4e38f; i1[s] = 0; }

    const uint32_t aLane = (uint32_t)((l & 15) * ASTRIDE + ((l >> 4) & 1) * 16);
    const uint32_t bLane = (uint32_t)((((l & 7) + ((l >> 4) << 3)) * ASTRIDE) + ((l >> 3) & 1) * 16);
    const uint32_t aBase = sb + A_OFF + (uint32_t)wm * 8704 + aLane;

    for (int c = 0; c < NCHUNK; c++) {
        if (c + 1 < NCHUNK) cp_wait1(); else cp_wait0();
        __syncthreads();           // stage (c&1) ready; A visible on first iter

        float acc[2][4][4];
        #pragma unroll
        for (int mi = 0; mi < 2; mi++)
            #pragma unroll
            for (int ni = 0; ni < 4; ni++)
                #pragma unroll
                for (int k = 0; k < 4; k++) acc[mi][ni][k] = 0.f;

        const uint32_t bBase = sb + B_OFF + (uint32_t)(c & 1) * BSTAGE
                             + (uint32_t)wn * 8704 + bLane;
        #pragma unroll
        for (int ks = 0; ks < 8; ks++) {
            uint32_t ak = aBase + (uint32_t)ks * 32;
            uint32_t bk = bBase + (uint32_t)ks * 32;
            uint32_t Ah[2][4];
            ldsm4(Ah[0], ak);            ldsm4(Ah[1], ak + 4352);
            uint32_t Bh[2][4], Bl[2][4];
            ldsm4(Bh[0], bk);            ldsm4(Bh[1], bk + 4352);
            ldsm4(Bl[0], bk + BMAT);     ldsm4(Bl[1], bk + BMAT + 4352);
            #pragma unroll
            for (int mi = 0; mi < 2; mi++)
                #pragma unroll
                for (int np = 0; np < 2; np++)
                    #pragma unroll
                    for (int ah = 0; ah < 2; ah++) {
                        float* C = acc[mi][np * 2 + ah];
                        mma16816(C, Ah[mi], &Bh[np][2 * ah]);   // xh * Eh
                        mma16816(C, Ah[mi], &Bl[np][2 * ah]);   // xh * El
                    }
        }

        __syncthreads();           // all warps done reading stage (c&1)
        if (c + 2 < NCHUNK) { load_b(sb, c + 2, c & 1, tid); cp_commit(); }

        // epilogue: s = acc/16 - ||e||^2 ; top-2 update (overlaps cp flight)
        const int cb = c * NC;
        #pragma unroll
        for (int mi = 0; mi < 2; mi++)
            #pragma unroll
            for (int ni = 0; ni < 4; ni++) {
                int col0 = cb + wn * 32 + ni * 8 + (l & 3) * 2;
                float2 en = *reinterpret_cast<float2*>(&s_en[col0]);
                #pragma unroll
                for (int h = 0; h < 2; h++) {
                    int s = mi * 2 + h;
                    float v0 = fmaf(acc[mi][ni][2 * h + 0], 0.0625f, -en.x);
                    float v1 = fmaf(acc[mi][ni][2 * h + 1], 0.0625f, -en.y);
                    if (v0 > b1[s]) { b2[s] = b1[s]; b1[s] = v0; i1[s] = col0; }
                    else if (v0 > b2[s]) b2[s] = v0;
                    if (v1 > b1[s]) { b2[s] = b1[s]; b1[s] = v1; i1[s] = col0 + 1; }
                    else if (v1 > b2[s]) b2[s] = v1;
                }
            }
    }

    // ---- quad-shfl top-2 merge, stage per-wn into smem ----
    __syncthreads();
    float* rv1 = reinterpret_cast<float*>(smm + RV1_OFF);
    float* rv2 = reinterpret_cast<float*>(smm + RV2_OFF);
    int*   ri1 = reinterpret_cast<int*>(smm + RI1_OFF);
    #pragma unroll
    for (int s = 0; s < 4; s++) {
        float v1 = b1[s], v2 = b2[s];
        int   k1 = i1[s];
        #pragma unroll
        for (int off = 1; off < 4; off <<= 1) {
            float ov1 = __shfl_xor_sync(0xffffffffu, v1, off);
            float ov2 = __shfl_xor_sync(0xffffffffu, v2, off);
            int   ok1 = __shfl_xor_sync(0xffffffffu, k1, off);
            if (ov1 > v1 || (ov1 == v1 && ok1 < k1)) {
                v2 = fmaxf(v1, ov2); v1 = ov1; k1 = ok1;
            } else {
                v2 = fmaxf(v2, ov1);
            }
        }
        if ((l & 3) == 0) {
            int mi = s >> 1, h = s & 1;
            int row = wm * 32 + mi * 16 + (l >> 2) + h * 8;
            rv1[wn * 128 + row] = v1;
            rv2[wn * 128 + row] = v2;
            ri1[wn * 128 + row] = k1;
        }
    }
    __syncthreads();

    // ---- final merge of 2 N-halves, certify or flag ----
    int* sbi = reinterpret_cast<int*>(smm + SBI_OFF);
    if (tid < 128) {
        float va = rv1[tid],       vb = rv1[128 + tid];
        float wa = rv2[tid],       wb = rv2[128 + tid];
        int   ka = ri1[tid],       kb = ri1[128 + tid];
        int   kwin;
        float m1;
        if (vb > va || (vb == va && kb < ka)) { m1 = vb; kwin = kb; }
        else                                  { m1 = va; kwin = ka; }
        float m2 = fmaxf(fmaxf(fminf(va, vb), wa), wb);
        sbi[tid] = kwin;
        if (write_idx)
            out[(long long)nrows * DDIM + rowBase + tid] = (float)kwin;
        if (m1 - m2 <= s_T[tid]) {
            int pos = atomicAdd(&g_cnt, 1);
            g_list[pos] = rowBase + tid;
        }
    }
    __syncthreads();

    // ---- gather winning codewords ----
    {
        float4* go = reinterpret_cast<float4*>(out);
        const float4* ge = reinterpret_cast<const float4*>(embed);
        #pragma unroll
        for (int i = 0; i < 16; i++) {
            int idx = tid + i * TH;
            int row = idx >> 5;
            int c4  = idx & 31;
            int k = sbi[row];
            go[((long long)(rowBase + row) << 5) + c4] = ge[(k << 5) + c4];
        }
    }
}

// ---------------- phase 2: exact fp32 rescan of flagged rows ----------------
__global__ __launch_bounds__(256, 4)
void fb_kernel(const float* __restrict__ x, const float* __restrict__ embed,
               float* __restrict__ out, int nrows, int write_idx) {
    __shared__ float sx[32][132];
    __shared__ float se[32 * 128];
    __shared__ float sen[KCB];
    __shared__ int   srows[32];
    __shared__ float sredv[8][32];
    __shared__ int   sredi[8][32];
    __shared__ int   sfin[32];

    const int tid = threadIdx.x;
    const int l = tid & 31;
    const int w = tid >> 5;

    #pragma unroll
    for (int i = 0; i < 4; i++) sen[tid + i * 256] = g_enorm[tid + i * 256];
    const int cnt = g_cnt;

    for (int b = blockIdx.x; b * 32 < cnt; b += gridDim.x) {
        int n = cnt - b * 32; if (n > 32) n = 32;
        if (tid < 32) srows[tid] = (tid < n) ? g_list[b * 32 + tid] : g_list[b * 32];
        __syncthreads();
        #pragma unroll
        for (int i = 0; i < 4; i++) {
            int idx = tid + i * 256;
            int j = idx >> 5, seg = idx & 31;
            float4 v = reinterpret_cast<const float4*>(x)[(long long)srows[j] * 32 + seg];
            *reinterpret_cast<float4*>(&sx[j][seg * 4]) = v;
        }

        float best = -3.4e38f;
        int   bi = 0;
        for (int ch = 0; ch < 32; ch++) {
            __syncthreads();
            #pragma unroll
            for (int i = 0; i < 4; i++) {
                int idx = tid + i * 256;
                int cr = idx >> 5, seg = idx & 31;
                float4 v = reinterpret_cast<const float4*>(embed)[((long long)ch * 32 + cr) * 32 + seg];
                *reinterpret_cast<float4*>(&se[cr * 128 + seg * 4]) = v;
            }
            __syncthreads();
            float acc[4] = {0.f, 0.f, 0.f, 0.f};
            #pragma unroll 8
            for (int d4 = 0; d4 < 32; d4++) {
                float4 xv = *reinterpret_cast<float4*>(&sx[l][d4 * 4]);
                #pragma unroll
                for (int m = 0; m < 4; m++) {
                    float4 ev = *reinterpret_cast<float4*>(&se[(w * 4 + m) * 128 + d4 * 4]);
                    acc[m] = fmaf(xv.x, ev.x, acc[m]);
                    acc[m] = fmaf(xv.y, ev.y, acc[m]);
                    acc[m] = fmaf(xv.z, ev.z, acc[m]);
                    acc[m] = fmaf(xv.w, ev.w, acc[m]);
                }
            }
            #pragma unroll
            for (int m = 0; m < 4; m++) {
                int k = ch * 32 + w * 4 + m;
                float s = fmaf(2.f, acc[m], -sen[k]);
                if (s > best || (s == best && k < bi)) { best = s; bi = k; }
            }
        }
        sredv[w][l] = best;
        sredi[w][l] = bi;
        __syncthreads();
        if (tid < 32) {
            float bv = sredv[0][tid];
            int   bk = sredi[0][tid];
            #pragma unroll
            for (int q = 1; q < 8; q++) {
                float v = sredv[q][tid];
                int   k = sredi[q][tid];
                if (v > bv || (v == bv && k < bk)) { bv = v; bk = k; }
            }
            sfin[tid] = bk;
            if (tid < n && write_idx)
                out[(long long)nrows * DDIM + srows[tid]] = (float)bk;
        }
        __syncthreads();
        #pragma unroll
        for (int i = 0; i < 4; i++) {
            int idx = tid + i * 256;
            int j = idx >> 5, c4 = idx & 31;
            if (j < n) {
                int k = sfin[j];
                reinterpret_cast<float4*>(out)[(long long)srows[j] * 32 + c4] =
                    reinterpret_cast<const float4*>(embed)[(long long)k * 32 + c4];
            }
        }
        __syncthreads();
    }
}

extern "C" void kernel_launch(void* const* d_in, const int* in_sizes, int n_in,
                              void* d_out, int out_size) {
    const float* x     = (const float*)d_in[0];
    const float* embed = (const float*)d_in[1];
    float* out = (float*)d_out;

    int nrows = in_sizes[0] / DDIM;  // 96000
    int write_idx = (out_size >= nrows * DDIM + nrows) ? 1 : 0;

    prep_kernel<<<(KCB * DDIM + 255) / 256, 256>>>(embed);

    cudaFuncSetAttribute(vq1_kernel,
                         cudaFuncAttributeMaxDynamicSharedMemorySize, SMEM_TOTAL);
    vq1_kernel<<<nrows / MT, TH, SMEM_TOTAL>>>(x, embed, out, nrows, write_idx);

    fb_kernel<<<296, 256>>>(x, embed, out, nrows, write_idx);
}

// round 17
// speedup vs baseline: 1.8164x; 1.4082x over previous
#include <cuda_runtime.h>
#include <cuda_fp16.h>
#include <cstdint>

#define DDIM 128
#define KCB  1024
#define MT   128          // rows per CTA
#define NC   64           // codes per chunk
#define NCHUNK 16
#define TH   256

#define ESCALE 32.0f        // embed pre-scale (power of 2)
#define INV2ESCALE 0.0625f  // 2/32

#define ASTRIDE 272                   // bytes per smem row (LDSM conflict-free)
#define AMAT   (128 * ASTRIDE)        // 34816 B per A term matrix
#define BMAT   (64 * ASTRIDE)         // 17408 B per B term matrix
#define A_OFF  0                      // A: h,l consecutive (2*AMAT = 69632)
#define B_OFF  (2 * AMAT)             // 69632; single stage, 2 terms
#define EN_OFF (B_OFF + 2 * BMAT)     // 104448: 1024 floats
#define RED_OFF (EN_OFF + 4096)       // 108544: val f32[256] + idx i32[256]
#define SMEM_TOTAL (RED_OFF + 2048)   // 110592  -> 2 CTAs/SM

__device__ float g_enorm[KCB];
__device__ __align__(16) unsigned short g_fsplit[2][KCB][DDIM];  // fp16 bits of 32*embed: h,l

// ---------------- PTX helpers (baseline ISA only) ----------------
static __device__ __forceinline__ uint32_t smem_u32(const void* p) {
    uint32_t a;
    asm("{ .reg .u64 t; cvta.to.shared.u64 t, %1; cvt.u32.u64 %0, t; }"
        : "=r"(a) : "l"(p));
    return a;
}
static __device__ __forceinline__ void ldsm4(uint32_t* r, uint32_t a) {
    asm volatile("ldmatrix.sync.aligned.m8n8.x4.shared.b16 {%0,%1,%2,%3}, [%4];"
                 : "=r"(r[0]), "=r"(r[1]), "=r"(r[2]), "=r"(r[3]) : "r"(a));
}
static __device__ __forceinline__ void mma16816(float* c, const uint32_t* a,
                                                const uint32_t* b2) {
    asm volatile(
        "mma.sync.aligned.m16n8k16.row.col.f32.f16.f16.f32 "
        "{%0,%1,%2,%3}, {%4,%5,%6,%7}, {%8,%9}, {%0,%1,%2,%3};"
        : "+f"(c[0]), "+f"(c[1]), "+f"(c[2]), "+f"(c[3])
        : "r"(a[0]), "r"(a[1]), "r"(a[2]), "r"(a[3]), "r"(b2[0]), "r"(b2[1]));
}
static __device__ __forceinline__ void cpasync16(uint32_t dst, const void* src) {
    asm volatile("cp.async.cg.shared.global [%0], [%1], 16;" :: "r"(dst), "l"(src));
}
static __device__ __forceinline__ void cp_commit() {
    asm volatile("cp.async.commit_group;" ::: "memory");
}
static __device__ __forceinline__ void cp_wait0() {
    asm volatile("cp.async.wait_group 0;" ::: "memory");
}
static __device__ __forceinline__ unsigned short hbits(__half h) {
    return *reinterpret_cast<unsigned short*>(&h);
}

// ---------------- fused prep kernel: split (vectorized) + enorm ----------------
__global__ void prep_kernel(const float* __restrict__ embed) {
    int t = blockIdx.x * blockDim.x + threadIdx.x;   // 0..32767
    if (t < KCB * DDIM / 4) {
        float4 v = reinterpret_cast<const float4*>(embed)[t];
        float vv[4] = {v.x, v.y, v.z, v.w};
        unsigned short hb[4], lb[4];
        #pragma unroll
        for (int j = 0; j < 4; j++) {
            float E = vv[j] * ESCALE;
            __half h = __float2half_rn(E);
            float r = E - __half2float(h);
            __half lo = __float2half_rn(r);
            hb[j] = hbits(h); lb[j] = hbits(lo);
        }
        uint2 uh = { (uint32_t)hb[0] | ((uint32_t)hb[1] << 16),
                     (uint32_t)hb[2] | ((uint32_t)hb[3] << 16) };
        uint2 ul = { (uint32_t)lb[0] | ((uint32_t)lb[1] << 16),
                     (uint32_t)lb[2] | ((uint32_t)lb[3] << 16) };
        reinterpret_cast<uint2*>(&g_fsplit[0][0][0])[t] = uh;
        reinterpret_cast<uint2*>(&g_fsplit[1][0][0])[t] = ul;
    }
    // blocks 0-3 also compute ||e||^2 (one row per thread)
    if (blockIdx.x < 4) {
        int row = blockIdx.x * blockDim.x + threadIdx.x;   // 0..1023
        const float4* rp = reinterpret_cast<const float4*>(embed + (long long)row * DDIM);
        float s = 0.f;
        #pragma unroll
        for (int j = 0; j < DDIM / 4; j++) {
            float4 v = rp[j];
            s = fmaf(v.x, v.x, s); s = fmaf(v.y, v.y, s);
            s = fmaf(v.z, v.z, s); s = fmaf(v.w, v.w, s);
        }
        g_enorm[row] = s;
    }
}

// ---------------- B chunk loader (cp.async, 2 terms x 64 rows x 256B) ----------------
static __device__ __forceinline__ void load_b(uint32_t sb, int c, int tid) {
    uint32_t dbase = sb + B_OFF;
    const char* gb = reinterpret_cast<const char*>(&g_fsplit[0][0][0]);
    #pragma unroll
    for (int i = 0; i < 8; i++) {
        int e = tid + i * TH;         // 0..2047  (2 terms x 64 rows x 16 segs)
        int t   = e >> 10;
        int rr  = (e >> 4) & 63;
        int seg = e & 15;
        const char* src = gb + ((size_t)t * KCB + (size_t)c * NC + rr) * 256 + seg * 16;
        uint32_t dst = dbase + (uint32_t)t * BMAT + (uint32_t)rr * ASTRIDE + seg * 16;
        cpasync16(dst, src);
    }
}

// ---------------- main kernel ----------------
__global__ __launch_bounds__(TH, 2)
void vq_kernel(const float* __restrict__ x, const float* __restrict__ embed,
               float* __restrict__ out, int nrows, int write_idx) {
    extern __shared__ __align__(16) char smm[];
    const uint32_t sb = smem_u32(smm);
    const int tid = threadIdx.x;
    const int l = tid & 31;
    const int w = tid >> 5;
    const int wm = w & 3;      // M-warp: rows wm*32
    const int wn = w >> 2;     // N-warp: cols wn*32 within 64-chunk
    const int rowBase = blockIdx.x * MT;

    float* s_en = reinterpret_cast<float*>(smm + EN_OFF);
    #pragma unroll
    for (int i = 0; i < 4; i++) s_en[tid + i * TH] = g_enorm[tid + i * TH];

    // prefetch B chunk 0
    load_b(sb, 0, tid);
    cp_commit();

    // A: load x rows, 2-term fp16 split into smem (x unscaled)
    {
        const float4* gx = reinterpret_cast<const float4*>(x + (long long)rowBase * DDIM);
        #pragma unroll
        for (int i = 0; i < 16; i++) {
            int fi = tid + i * TH;             // 0..4095
            int r = fi >> 5;
            int k = (fi & 31) * 4;
            float4 v = gx[fi];
            float vv[4] = {v.x, v.y, v.z, v.w};
            unsigned short hb[4], lb[4];
            #pragma unroll
            for (int j = 0; j < 4; j++) {
                __half h = __float2half_rn(vv[j]);
                float rr = vv[j] - __half2float(h);
                __half lo = __float2half_rn(rr);
                hb[j] = hbits(h); lb[j] = hbits(lo);
            }
            uint32_t off = (uint32_t)r * ASTRIDE + (uint32_t)k * 2;
            uint2 uh = { (uint32_t)hb[0] | ((uint32_t)hb[1] << 16),
                         (uint32_t)hb[2] | ((uint32_t)hb[3] << 16) };
            uint2 ul = { (uint32_t)lb[0] | ((uint32_t)lb[1] << 16),
                         (uint32_t)lb[2] | ((uint32_t)lb[3] << 16) };
            *reinterpret_cast<uint2*>(smm + A_OFF + 0 * AMAT + off) = uh;
            *reinterpret_cast<uint2*>(smm + A_OFF + 1 * AMAT + off) = ul;
        }
    }

    float best[2][2];
    int   bidx[2][2];
    #pragma unroll
    for (int a = 0; a < 2; a++)
        #pragma unroll
        for (int b = 0; b < 2; b++) { best[a][b] = -3.4e38f; bidx[a][b] = 0; }

    // ldmatrix lane address offsets (validated R7-R9)
    const uint32_t aLane = (uint32_t)((l & 15) * ASTRIDE + ((l >> 4) & 1) * 16);
    const uint32_t bLane = (uint32_t)((((l & 7) + ((l >> 4) << 3)) * ASTRIDE) + ((l >> 3) & 1) * 16);
    const uint32_t aBase = sb + A_OFF + (uint32_t)wm * 8704 + aLane;
    const uint32_t bBase0 = sb + B_OFF + (uint32_t)wn * 8704 + bLane;

    for (int c = 0; c < NCHUNK; c++) {
        cp_wait0();
        __syncthreads();          // B(c) ready in smem (and A visible on first iter)

        float acc[2][4][4];
        #pragma unroll
        for (int mi = 0; mi < 2; mi++)
            #pragma unroll
            for (int ni = 0; ni < 4; ni++)
                #pragma unroll
                for (int k = 0; k < 4; k++) acc[mi][ni][k] = 0.f;

        #pragma unroll
        for (int ks = 0; ks < 8; ks++) {
            uint32_t ak = aBase + (uint32_t)ks * 32;
            uint32_t bk = bBase0 + (uint32_t)ks * 32;
            // batch 1: Ah + Bh, then the hh pass (8 MMAs) while Al/Bl loads fly
            uint32_t Ah[2][4], Bh[2][4];
            ldsm4(Ah[0], ak);            ldsm4(Ah[1], ak + 4352);
            ldsm4(Bh[0], bk);            ldsm4(Bh[1], bk + 4352);
            uint32_t Al[2][4], Bl[2][4];
            ldsm4(Al[0], ak + AMAT);     ldsm4(Al[1], ak + AMAT + 4352);
            #pragma unroll
            for (int mi = 0; mi < 2; mi++)
                #pragma unroll
                for (int np = 0; np < 2; np++)
                    #pragma unroll
                    for (int ah = 0; ah < 2; ah++)
                        mma16816(acc[mi][np * 2 + ah], Ah[mi], &Bh[np][2 * ah]);  // h*h
            ldsm4(Bl[0], bk + BMAT);     ldsm4(Bl[1], bk + BMAT + 4352);
            #pragma unroll
            for (int mi = 0; mi < 2; mi++)
                #pragma unroll
                for (int np = 0; np < 2; np++)
                    #pragma unroll
                    for (int ah = 0; ah < 2; ah++)
                        mma16816(acc[mi][np * 2 + ah], Al[mi], &Bh[np][2 * ah]);  // l*h
            #pragma unroll
            for (int mi = 0; mi < 2; mi++)
                #pragma unroll
                for (int np = 0; np < 2; np++)
                    #pragma unroll
                    for (int ah = 0; ah < 2; ah++)
                        mma16816(acc[mi][np * 2 + ah], Ah[mi], &Bl[np][2 * ah]);  // h*l
        }

        // all warps done READING B(c) -> barrier, then immediately launch
        // the next chunk's cp.async so its flight overlaps the epilogue below
        __syncthreads();
        if (c + 1 < NCHUNK) {
            load_b(sb, c + 1, tid);
            cp_commit();
        }

        // epilogue: score = 2*(dot/32) - ||e||^2, per-thread argmax
        const int cb = c * NC;
        #pragma unroll
        for (int mi = 0; mi < 2; mi++)
            #pragma unroll
            for (int ni = 0; ni < 4; ni++) {
                int col0 = cb + wn * 32 + ni * 8 + (l & 3) * 2;
                float2 en = *reinterpret_cast<float2*>(&s_en[col0]);
                float s0 = fmaf(INV2ESCALE, acc[mi][ni][0], -en.x);
                float s1 = fmaf(INV2ESCALE, acc[mi][ni][1], -en.y);
                float s2 = fmaf(INV2ESCALE, acc[mi][ni][2], -en.x);
                float s3 = fmaf(INV2ESCALE, acc[mi][ni][3], -en.y);
                if (s0 > best[mi][0]) { best[mi][0] = s0; bidx[mi][0] = col0; }
                if (s1 > best[mi][0]) { best[mi][0] = s1; bidx[mi][0] = col0 + 1; }
                if (s2 > best[mi][1]) { best[mi][1] = s2; bidx[mi][1] = col0; }
                if (s3 > best[mi][1]) { best[mi][1] = s3; bidx[mi][1] = col0 + 1; }
            }
    }

    // ---- reduce: quad shfl, then cross-N-warp smem merge ----
    float* sval = reinterpret_cast<float*>(smm + RED_OFF);
    int*   sidx = reinterpret_cast<int*>(smm + RED_OFF + 1024);
    #pragma unroll
    for (int mi = 0; mi < 2; mi++)
        #pragma unroll
        for (int h = 0; h < 2; h++) {
            float v = best[mi][h];
            int   k = bidx[mi][h];
            #pragma unroll
            for (int off = 1; off < 4; off <<= 1) {
                float ov = __shfl_xor_sync(0xffffffffu, v, off);
                int   oi = __shfl_xor_sync(0xffffffffu, k, off);
                if (ov > v || (ov == v && oi < k)) { v = ov; k = oi; }
            }
            if ((l & 3) == 0) {
                int row = wm * 32 + mi * 16 + (l >> 2) + h * 8;
                sval[wn * 128 + row] = v;
                sidx[wn * 128 + row] = k;
            }
        }
    __syncthreads();

    int* sbi = reinterpret_cast<int*>(smm + RED_OFF);   // reuse sval region
    if (tid < 128) {
        float v0 = sval[tid], v1 = sval[128 + tid];
        int   k0 = sidx[tid], k1 = sidx[128 + tid];
        int k = (v1 > v0 || (v1 == v0 && k1 < k0)) ? k1 : k0;
        sbi[tid] = k;
        if (write_idx)
            out[(long long)nrows * DDIM + rowBase + tid] = (float)k;
    }
    __syncthreads();

    // ---- gather winning codewords (coalesced float4) ----
    {
        float4* go = reinterpret_cast<float4*>(out);
        const float4* ge = reinterpret_cast<const float4*>(embed);
        #pragma unroll
        for (int i = 0; i < 16; i++) {
            int idx = tid + i * TH;        // [128 rows][32 f4]
            int row = idx >> 5;
            int c4  = idx & 31;
            int k = sbi[row];
            go[((long long)(rowBase + row) << 5) + c4] = ge[(k << 5) + c4];
        }
    }
}

extern "C" void kernel_launch(void* const* d_in, const int* in_sizes, int n_in,
                              void* d_out, int out_size) {
    const float* x     = (const float*)d_in[0];
    const float* embed = (const float*)d_in[1];
    float* out = (float*)d_out;

    int nrows = in_sizes[0] / DDIM;  // 96000
    int write_idx = (out_size >= nrows * DDIM + nrows) ? 1 : 0;

    prep_kernel<<<128, 256>>>(embed);

    cudaFuncSetAttribute(vq_kernel,
                         cudaFuncAttributeMaxDynamicSharedMemorySize, SMEM_TOTAL);
    vq_kernel<<<nrows / MT, TH, SMEM_TOTAL>>>(x, embed, out, nrows, write_idx);
}